// round 1
// baseline (speedup 1.0000x reference)
#include <cuda_runtime.h>
#include <math.h>

#define B_ 256
#define L_ 32
#define D_ 512
#define H_ 512

// ---------------- scratch (device globals; no allocation allowed) -----------
__device__ float g_h    [B_ * L_ * H_];   // node h, keyed (batch, slot)
__device__ float g_c    [B_ * L_ * H_];   // node c
__device__ float g_comph[B_ * L_ * H_];   // pair comp h, keyed by LEFT slot
__device__ float g_compc[B_ * L_ * H_];   // pair comp c
__device__ float g_lgpart[B_ * L_ * 16];  // per-jtile partial dots (deterministic logit)
__device__ int   g_order[B_ * L_];        // active slot list per batch
__device__ int4  g_tasks[2 * B_];         // {valid, b, ls, rs} recompute tasks

__device__ __forceinline__ float sigf(float x) { return 1.0f / (1.0f + expf(-x)); }

// ---------------- init: order[b][j] = j ------------------------------------
__global__ void init_kernel() {
    int idx = blockIdx.x * blockDim.x + threadIdx.x;
    if (idx < B_ * L_) g_order[idx] = idx & 31;
}

// ---------------- word projection: hc = x @ W_word^T + b_word ---------------
// M = 8192 (b*32+l), K = 512, N = 1024. BM=BN=128, BK=16, 256 thr, TM=TN=8.
__global__ __launch_bounds__(256) void word_kernel(
    const float* __restrict__ x, const float* __restrict__ Ww,
    const float* __restrict__ bw) {
    __shared__ float Xs[16][132];
    __shared__ float Ws[16][132];
    int tid = threadIdx.x;
    int tx = tid & 15, ty = tid >> 4;
    int m0 = blockIdx.x * 128, n0 = blockIdx.y * 128;

    float acc[8][8];
#pragma unroll
    for (int i = 0; i < 8; i++)
#pragma unroll
        for (int j = 0; j < 8; j++) acc[i][j] = 0.f;

    for (int kc = 0; kc < 32; kc++) {
        int k0 = kc * 16;
#pragma unroll
        for (int rep = 0; rep < 2; rep++) {
            int idx = tid + rep * 256;
            int row = idx >> 2;
            int kq  = (idx & 3) * 4;
            float4 xa = *(const float4*)&x [(size_t)(m0 + row) * 512 + k0 + kq];
            float4 wa = *(const float4*)&Ww[(size_t)(n0 + row) * 512 + k0 + kq];
            Xs[kq + 0][row] = xa.x; Xs[kq + 1][row] = xa.y;
            Xs[kq + 2][row] = xa.z; Xs[kq + 3][row] = xa.w;
            Ws[kq + 0][row] = wa.x; Ws[kq + 1][row] = wa.y;
            Ws[kq + 2][row] = wa.z; Ws[kq + 3][row] = wa.w;
        }
        __syncthreads();
#pragma unroll
        for (int kk = 0; kk < 16; kk++) {
            float a[8], w[8];
#pragma unroll
            for (int i = 0; i < 8; i++) a[i] = Xs[kk][ty * 8 + i];
#pragma unroll
            for (int j = 0; j < 8; j++) w[j] = Ws[kk][tx * 8 + j];
#pragma unroll
            for (int i = 0; i < 8; i++)
#pragma unroll
                for (int j = 0; j < 8; j++) acc[i][j] += a[i] * w[j];
        }
        __syncthreads();
    }
#pragma unroll
    for (int i = 0; i < 8; i++) {
        int m = m0 + ty * 8 + i;
#pragma unroll
        for (int j = 0; j < 8; j++) {
            int n = n0 + tx * 8 + j;
            float v = acc[i][j] + bw[n];
            if (n < 512) g_h[(size_t)m * 512 + n] = v;
            else         g_c[(size_t)m * 512 + n - 512] = v;
        }
    }
}

// ---------------- compose GEMM + TreeLSTM gate epilogue ---------------------
// Rows = tasks (gathered concat(h[ls],h[rs])), K = 1024, J = 512, 5 gates.
// BM=64, BJ=32, BK=32, 256 thr (tx=16 j, ty=16 m), TM=4, TJ=2, 40 acc.
__global__ __launch_bounds__(256) void compose_kernel(
    const float* __restrict__ Wc, const float* __restrict__ bc,
    const float* __restrict__ cq, int initial, int ntasks) {
    __shared__ float As[32][68];
    __shared__ float Ws[5][32][34];
    __shared__ int sb[64], sls[64], srs[64];

    int tid  = threadIdx.x;
    int row0 = blockIdx.x * 64;
    int j0   = blockIdx.y * 32;

    int v = 0;
    if (tid < 64) {
        int t = row0 + tid;
        int b = -1, ls = 0, rs = 0;
        if (t < ntasks) {
            if (initial) { b = t / 31; int p = t - b * 31; ls = p; rs = p + 1; v = 1; }
            else { int4 tk = g_tasks[t]; if (tk.x) { b = tk.y; ls = tk.z; rs = tk.w; v = 1; } }
        }
        sb[tid] = b; sls[tid] = ls; srs[tid] = rs;
    }
    int any = __syncthreads_or(v);
    if (!any) return;

    int tx = tid & 15, ty = tid >> 4;
    float acc[5][4][2];
#pragma unroll
    for (int g = 0; g < 5; g++)
#pragma unroll
        for (int q = 0; q < 4; q++) { acc[g][q][0] = 0.f; acc[g][q][1] = 0.f; }

    for (int kc = 0; kc < 32; kc++) {
        int k0 = kc * 32;
        // A tile: 64 rows x 32 k (left slot for k<512, right slot for k>=512)
#pragma unroll
        for (int rep = 0; rep < 2; rep++) {
            int idx = tid + rep * 256;
            int row = idx >> 3;
            int kq  = (idx & 7) * 4;
            float4 a4 = make_float4(0.f, 0.f, 0.f, 0.f);
            int b = sb[row];
            if (b >= 0) {
                int slot = (k0 < 512) ? sls[row] : srs[row];
                a4 = *(const float4*)&g_h[((size_t)((b << 5) + slot)) * 512 + (k0 & 511) + kq];
            }
            As[kq + 0][row] = a4.x; As[kq + 1][row] = a4.y;
            As[kq + 2][row] = a4.z; As[kq + 3][row] = a4.w;
        }
        // W tiles: 5 gates x 32 j x 32 k
#pragma unroll
        for (int rep = 0; rep < 5; rep++) {
            int idx = tid + rep * 256;
            int r  = idx >> 3;
            int g  = r >> 5;
            int j  = r & 31;
            int kq = (idx & 7) * 4;
            float4 w4 = *(const float4*)&Wc[((size_t)(g * 512 + j0 + j)) * 1024 + k0 + kq];
            Ws[g][kq + 0][j] = w4.x; Ws[g][kq + 1][j] = w4.y;
            Ws[g][kq + 2][j] = w4.z; Ws[g][kq + 3][j] = w4.w;
        }
        __syncthreads();
#pragma unroll
        for (int kk = 0; kk < 32; kk++) {
            float4 a4 = *(const float4*)&As[kk][ty * 4];
            float a[4] = {a4.x, a4.y, a4.z, a4.w};
            float w[5][2];
#pragma unroll
            for (int g = 0; g < 5; g++) {
                float2 w2 = *(const float2*)&Ws[g][kk][tx * 2];
                w[g][0] = w2.x; w[g][1] = w2.y;
            }
#pragma unroll
            for (int g = 0; g < 5; g++)
#pragma unroll
                for (int q = 0; q < 4; q++) {
                    acc[g][q][0] += a[q] * w[g][0];
                    acc[g][q][1] += a[q] * w[g][1];
                }
        }
        __syncthreads();
    }

    // epilogue: gates -> (h,c) comp + per-jtile partial of logit dot
    float qv[2] = { cq[j0 + tx * 2], cq[j0 + tx * 2 + 1] };
    float bb[5][2];
#pragma unroll
    for (int g = 0; g < 5; g++) {
        bb[g][0] = bc[g * 512 + j0 + tx * 2];
        bb[g][1] = bc[g * 512 + j0 + tx * 2 + 1];
    }
#pragma unroll
    for (int q = 0; q < 4; q++) {
        int lrow = ty * 4 + q;
        int b = sb[lrow];
        float partial = 0.f;
        if (b >= 0) {
            int ls = sls[lrow], rs = srs[lrow];
            size_t obase = ((size_t)((b << 5) + ls)) * 512;
            size_t rbase = ((size_t)((b << 5) + rs)) * 512;
#pragma unroll
            for (int e = 0; e < 2; e++) {
                int j = j0 + tx * 2 + e;
                float iv = acc[0][q][e] + bb[0][e];
                float fl = acc[1][q][e] + bb[1][e];
                float fr = acc[2][q][e] + bb[2][e];
                float uu = acc[3][q][e] + bb[3][e];
                float oo = acc[4][q][e] + bb[4][e];
                float cl = g_c[obase + j];
                float cr = g_c[rbase + j];
                float cn = cl * sigf(fl + 1.f) + cr * sigf(fr + 1.f)
                         + tanhf(uu) * sigf(iv);
                float hn = sigf(oo) * tanhf(cn);
                g_compc[obase + j] = cn;
                g_comph[obase + j] = hn;
                partial += qv[e] * hn;
            }
        }
        // reduce over the 16 tx lanes (same row); xor<=8 stays in the half-warp
#pragma unroll
        for (int off = 8; off; off >>= 1)
            partial += __shfl_xor_sync(0xffffffffu, partial, off);
        if (tx == 0 && b >= 0)
            g_lgpart[((b << 5) + sls[lrow]) * 16 + blockIdx.y] = partial;
    }
}

// ---------------- select + merge (1 warp per batch) -------------------------
__global__ __launch_bounds__(256) void select_kernel(const int* __restrict__ length,
                                                     int step) {
    int warp = threadIdx.x >> 5;
    int lane = threadIdx.x & 31;
    int b = blockIdx.x * 8 + warp;
    int len = length[b];

    if (step + 1 >= len) {                       // finished batch: clear tasks
        if (lane == 0) {
            g_tasks[2 * b]     = make_int4(0, 0, 0, 0);
            g_tasks[2 * b + 1] = make_int4(0, 0, 0, 0);
        }
        return;
    }

    int n    = 32 - step;        // current node count
    int vlim = len - step - 1;   // valid pair positions: j < vlim (>= 1)

    int myslot = (lane < n) ? g_order[(b << 5) + lane] : 0;

    float lg = -1e30f;
    if (lane < vlim) {           // deterministic 16-partial sum, fixed order
        const float* p = &g_lgpart[((b << 5) + myslot) * 16];
        float s = 0.f;
#pragma unroll
        for (int t = 0; t < 16; t++) s += p[t];
        lg = s * 0.04419417382415922f;   // 1/sqrt(512)
    }

    // argmax, first occurrence on ties (matches jnp.argmax)
    float bv = lg; int bi = lane;
#pragma unroll
    for (int off = 16; off; off >>= 1) {
        float ov = __shfl_down_sync(0xffffffffu, bv, off);
        int   oi = __shfl_down_sync(0xffffffffu, bi, off);
        if (ov > bv || (ov == bv && oi < bi)) { bv = ov; bi = oi; }
    }
    int p = __shfl_sync(0xffffffffu, bi, 0);

    int s    = __shfl_sync(0xffffffffu, myslot, p);
    int prev = __shfl_sync(0xffffffffu, myslot, (p > 0) ? (p - 1) : 0);
    int nxt2 = __shfl_sync(0xffffffffu, myslot, (p + 2 <= n - 1) ? (p + 2) : 0);
    int nxt  = __shfl_down_sync(0xffffffffu, myslot, 1);

    // merge: node s takes the composed value
    size_t base = ((size_t)((b << 5) + s)) * 128;   // float4 units
    float4*       h4  = (float4*)g_h;
    float4*       c4  = (float4*)g_c;
    const float4* ch4 = (const float4*)g_comph;
    const float4* cc4 = (const float4*)g_compc;
    for (int idx = lane; idx < 128; idx += 32) h4[base + idx] = ch4[base + idx];
    for (int idx = lane; idx < 128; idx += 32) c4[base + idx] = cc4[base + idx];

    // remove node at position p+1 from the order list
    if (lane >= p + 1 && lane <= n - 2) g_order[(b << 5) + lane] = nxt;

    // emit recompute tasks for the (at most two) new adjacent pairs
    if (lane == 0) {
        int4 t0 = make_int4(0, 0, 0, 0), t1 = make_int4(0, 0, 0, 0);
        if (p > 0)          t0 = make_int4(1, b, prev, s);
        if (p + 2 <= n - 1) t1 = make_int4(1, b, s, nxt2);
        g_tasks[2 * b]     = t0;
        g_tasks[2 * b + 1] = t1;
    }
}

// ---------------- output: h of slot 0 of each batch -------------------------
__global__ void out_kernel(float* __restrict__ out) {
    int idx = blockIdx.x * 256 + threadIdx.x;   // 131072 total
    int b = idx >> 9, j = idx & 511;
    out[idx] = g_h[((size_t)b << 14) + j];      // slot 0
}

// ---------------- launch ----------------------------------------------------
extern "C" void kernel_launch(void* const* d_in, const int* in_sizes, int n_in,
                              void* d_out, int out_size) {
    const float* x      = (const float*)d_in[0];
    const int*   length = (const int*)  d_in[1];
    const float* Ww     = (const float*)d_in[2];
    const float* bw     = (const float*)d_in[3];
    const float* Wc     = (const float*)d_in[4];
    const float* bc     = (const float*)d_in[5];
    const float* cq     = (const float*)d_in[6];

    init_kernel<<<32, 256>>>();
    word_kernel<<<dim3(64, 8), 256>>>(x, Ww, bw);
    // initial compose of all 31 adjacent pairs per batch (7936 rows)
    compose_kernel<<<dim3(124, 16), 256>>>(Wc, bc, cq, 1, 7936);
    for (int i = 0; i < 31; i++) {
        select_kernel<<<32, 256>>>(length, i);
        compose_kernel<<<dim3(8, 16), 256>>>(Wc, bc, cq, 0, 512);
    }
    out_kernel<<<512, 256>>>((float*)d_out);
    (void)in_sizes; (void)n_in; (void)out_size;
}

// round 2
// speedup vs baseline: 1.1090x; 1.1090x over previous
#include <cuda_runtime.h>
#include <math.h>
#include <stdint.h>

#define B_ 256
#define L_ 32
#define D_ 512
#define H_ 512

// ---------------- scratch (device globals; no allocation allowed) -----------
__device__ float g_h    [B_ * L_ * H_];   // node h, keyed (batch, slot)
__device__ float g_c    [B_ * L_ * H_];   // node c
__device__ float g_comph[B_ * L_ * H_];   // pair comp h, keyed by LEFT slot
__device__ float g_compc[B_ * L_ * H_];   // pair comp c
__device__ float g_lgpart[B_ * L_ * 32];  // per-16j-slice partial dots
__device__ int   g_order[B_ * L_];        // active slot list per batch
__device__ int4  g_tasks[2 * B_];         // {valid, b, ls, rs} recompute tasks

__device__ __forceinline__ float sigf(float x) { return 1.0f / (1.0f + expf(-x)); }

// exact 3-way bf16 split of an fp32 pair (truncation: 24 = 8+8+8 mantissa bits)
// packed bf16x2: low half = element k, high half = element k+1
__device__ __forceinline__ uint32_t split_pair(float x0, float x1, float& r0, float& r1) {
    uint32_t u0 = __float_as_uint(x0) & 0xffff0000u;
    uint32_t u1 = __float_as_uint(x1) & 0xffff0000u;
    r0 = x0 - __uint_as_float(u0);
    r1 = x1 - __uint_as_float(u1);
    return (u0 >> 16) | u1;
}
__device__ __forceinline__ uint4 split3(float x0, float x1) {
    float r0, r1, s0, s1;
    uint32_t p1 = split_pair(x0, x1, r0, r1);
    uint32_t p2 = split_pair(r0, r1, s0, s1);
    uint32_t p3 = (__float_as_uint(s0) >> 16) | (__float_as_uint(s1) & 0xffff0000u);
    return make_uint4(p1, p2, p3, 0u);
}

__device__ __forceinline__ void mma16816(float* d, const uint32_t* a,
                                         uint32_t b0, uint32_t b1) {
    asm volatile(
        "mma.sync.aligned.m16n8k16.row.col.f32.bf16.bf16.f32 "
        "{%0,%1,%2,%3}, {%4,%5,%6,%7}, {%8,%9}, {%0,%1,%2,%3};\n"
        : "+f"(d[0]), "+f"(d[1]), "+f"(d[2]), "+f"(d[3])
        : "r"(a[0]), "r"(a[1]), "r"(a[2]), "r"(a[3]), "r"(b0), "r"(b1));
}

// ---------------- init: order[b][j] = j ------------------------------------
__global__ void init_kernel() {
    int idx = blockIdx.x * blockDim.x + threadIdx.x;
    if (idx < B_ * L_) g_order[idx] = idx & 31;
}

// ---------------- word projection: hc = x @ W_word^T + b_word (fp32) --------
__global__ __launch_bounds__(256) void word_kernel(
    const float* __restrict__ x, const float* __restrict__ Ww,
    const float* __restrict__ bw) {
    __shared__ float Xs[16][132];
    __shared__ float Ws[16][132];
    int tid = threadIdx.x;
    int tx = tid & 15, ty = tid >> 4;
    int m0 = blockIdx.x * 128, n0 = blockIdx.y * 128;

    float acc[8][8];
#pragma unroll
    for (int i = 0; i < 8; i++)
#pragma unroll
        for (int j = 0; j < 8; j++) acc[i][j] = 0.f;

    for (int kc = 0; kc < 32; kc++) {
        int k0 = kc * 16;
#pragma unroll
        for (int rep = 0; rep < 2; rep++) {
            int idx = tid + rep * 256;
            int row = idx >> 2;
            int kq  = (idx & 3) * 4;
            float4 xa = *(const float4*)&x [(size_t)(m0 + row) * 512 + k0 + kq];
            float4 wa = *(const float4*)&Ww[(size_t)(n0 + row) * 512 + k0 + kq];
            Xs[kq + 0][row] = xa.x; Xs[kq + 1][row] = xa.y;
            Xs[kq + 2][row] = xa.z; Xs[kq + 3][row] = xa.w;
            Ws[kq + 0][row] = wa.x; Ws[kq + 1][row] = wa.y;
            Ws[kq + 2][row] = wa.z; Ws[kq + 3][row] = wa.w;
        }
        __syncthreads();
#pragma unroll
        for (int kk = 0; kk < 16; kk++) {
            float a[8], w[8];
#pragma unroll
            for (int i = 0; i < 8; i++) a[i] = Xs[kk][ty * 8 + i];
#pragma unroll
            for (int j = 0; j < 8; j++) w[j] = Ws[kk][tx * 8 + j];
#pragma unroll
            for (int i = 0; i < 8; i++)
#pragma unroll
                for (int j = 0; j < 8; j++) acc[i][j] += a[i] * w[j];
        }
        __syncthreads();
    }
#pragma unroll
    for (int i = 0; i < 8; i++) {
        int m = m0 + ty * 8 + i;
#pragma unroll
        for (int j = 0; j < 8; j++) {
            int n = n0 + tx * 8 + j;
            float v = acc[i][j] + bw[n];
            if (n < 512) g_h[(size_t)m * 512 + n] = v;
            else         g_c[(size_t)m * 512 + n - 512] = v;
        }
    }
}

// ---------------- compose GEMM (bf16x3 6-product HMMA) + gate epilogue ------
// BM=64 rows, BJ=32 j, 5 gates, BK=32. 8 warps: mw = w&3 (m16), jw = w>>2 (j16).
// Warp tile: m16 x j16 x 5 gates = 10 mma tiles, 6 bf16 products each.
#define SA_STRIDE 20
#define SB_STRIDE 20

__global__ __launch_bounds__(256, 2) void compose_mma(
    const float* __restrict__ Wc, const float* __restrict__ bc,
    const float* __restrict__ cq, int initial, int ntasks) {
    extern __shared__ uint4 dyn[];
    uint4* sA = dyn;                        // [64][SA_STRIDE]
    uint4* sB = dyn + 64 * SA_STRIDE;       // [5*32][SB_STRIDE]
    int*   sb  = (int*)(sB + 5 * 32 * SB_STRIDE);
    int*   sls = sb + 64;
    int*   srs = sls + 64;

    int tid  = threadIdx.x;
    int row0 = blockIdx.x * 64;
    int j0   = blockIdx.y * 32;

    int v = 0;
    if (tid < 64) {
        int t = row0 + tid;
        int b = -1, ls = 0, rs = 0;
        if (t < ntasks) {
            if (initial) { b = t / 31; int p = t - b * 31; ls = p; rs = p + 1; v = 1; }
            else { int4 tk = g_tasks[t]; if (tk.x) { b = tk.y; ls = tk.z; rs = tk.w; v = 1; } }
        }
        sb[tid] = b; sls[tid] = ls; srs[tid] = rs;
    }
    int any = __syncthreads_or(v);
    if (!any) return;

    int lane = tid & 31;
    int warp = tid >> 5;
    int mw = warp & 3;
    int jw = warp >> 2;
    int r = lane >> 2, q = lane & 3;

    float acc[5][2][4];
#pragma unroll
    for (int g = 0; g < 5; g++)
#pragma unroll
        for (int jt = 0; jt < 2; jt++)
#pragma unroll
            for (int e = 0; e < 4; e++) acc[g][jt][e] = 0.f;

    // ------- register double-buffered global loads -------
    float4 aReg[2];
    float4 bReg[5];
    {
        int k0 = 0;
#pragma unroll
        for (int rep = 0; rep < 2; rep++) {
            int idx = tid + rep * 256;
            int row = idx >> 3;
            int kq  = (idx & 7) * 4;
            float4 a4 = make_float4(0.f, 0.f, 0.f, 0.f);
            int b = sb[row];
            if (b >= 0) {
                int slot = sls[row];  // k0 = 0 < 512 -> left
                a4 = *(const float4*)&g_h[((size_t)((b << 5) + slot)) * 512 + kq];
            }
            aReg[rep] = a4;
        }
#pragma unroll
        for (int rep = 0; rep < 5; rep++) {
            int idx = tid + rep * 256;
            int jr  = idx >> 3;
            int kq  = (idx & 7) * 4;
            bReg[rep] = *(const float4*)&Wc[((size_t)((jr >> 5) * 512 + j0 + (jr & 31))) * 1024 + k0 + kq];
        }
    }

    for (int kc = 0; kc < 32; kc++) {
        // store current staged tile (convert fp32 -> 3x bf16 packed)
#pragma unroll
        for (int rep = 0; rep < 2; rep++) {
            int idx = tid + rep * 256;
            int row = idx >> 3;
            int kq  = (idx & 7) * 4;
            sA[row * SA_STRIDE + (kq >> 1)]     = split3(aReg[rep].x, aReg[rep].y);
            sA[row * SA_STRIDE + (kq >> 1) + 1] = split3(aReg[rep].z, aReg[rep].w);
        }
#pragma unroll
        for (int rep = 0; rep < 5; rep++) {
            int idx = tid + rep * 256;
            int jr  = idx >> 3;
            int kq  = (idx & 7) * 4;
            sB[jr * SB_STRIDE + (kq >> 1)]     = split3(bReg[rep].x, bReg[rep].y);
            sB[jr * SB_STRIDE + (kq >> 1) + 1] = split3(bReg[rep].z, bReg[rep].w);
        }
        __syncthreads();

        // prefetch next tile (latency overlaps compute below)
        if (kc + 1 < 32) {
            int k0 = (kc + 1) * 32;
#pragma unroll
            for (int rep = 0; rep < 2; rep++) {
                int idx = tid + rep * 256;
                int row = idx >> 3;
                int kq  = (idx & 7) * 4;
                float4 a4 = make_float4(0.f, 0.f, 0.f, 0.f);
                int b = sb[row];
                if (b >= 0) {
                    int slot = (k0 < 512) ? sls[row] : srs[row];
                    a4 = *(const float4*)&g_h[((size_t)((b << 5) + slot)) * 512 + (k0 & 511) + kq];
                }
                aReg[rep] = a4;
            }
#pragma unroll
            for (int rep = 0; rep < 5; rep++) {
                int idx = tid + rep * 256;
                int jr  = idx >> 3;
                int kq  = (idx & 7) * 4;
                bReg[rep] = *(const float4*)&Wc[((size_t)((jr >> 5) * 512 + j0 + (jr & 31))) * 1024 + k0 + kq];
            }
        }

        // compute: 2 k16 sub-steps
#pragma unroll
        for (int t = 0; t < 2; t++) {
            uint4 A0 = sA[(mw * 16 + r)     * SA_STRIDE + t * 8 + q];
            uint4 A1 = sA[(mw * 16 + r + 8) * SA_STRIDE + t * 8 + q];
            uint4 A2 = sA[(mw * 16 + r)     * SA_STRIDE + t * 8 + q + 4];
            uint4 A3 = sA[(mw * 16 + r + 8) * SA_STRIDE + t * 8 + q + 4];
            uint32_t a1f[4] = {A0.x, A1.x, A2.x, A3.x};
            uint32_t a2f[4] = {A0.y, A1.y, A2.y, A3.y};
            uint32_t a3f[4] = {A0.z, A1.z, A2.z, A3.z};
#pragma unroll
            for (int g = 0; g < 5; g++) {
#pragma unroll
                for (int jt = 0; jt < 2; jt++) {
                    int col = jw * 16 + jt * 8 + r;
                    uint4 B0 = sB[(g * 32 + col) * SB_STRIDE + t * 8 + q];
                    uint4 B1 = sB[(g * 32 + col) * SB_STRIDE + t * 8 + q + 4];
                    float* d = acc[g][jt];
                    mma16816(d, a1f, B0.x, B1.x);   // h1*b1
                    mma16816(d, a1f, B0.y, B1.y);   // h1*b2
                    mma16816(d, a2f, B0.x, B1.x);   // h2*b1
                    mma16816(d, a1f, B0.z, B1.z);   // h1*b3
                    mma16816(d, a2f, B0.y, B1.y);   // h2*b2
                    mma16816(d, a3f, B0.x, B1.x);   // h3*b1
                }
            }
        }
        __syncthreads();
    }

    // ------- epilogue: gates -> (h,c) comp + logit partial per 16-j slice ----
#pragma unroll
    for (int half = 0; half < 2; half++) {
        int lrow = mw * 16 + r + half * 8;
        int b = sb[lrow];
        float partial = 0.f;
        if (b >= 0) {
            int ls = sls[lrow], rs = srs[lrow];
            size_t ob = ((size_t)((b << 5) + ls)) * 512;
            size_t rb = ((size_t)((b << 5) + rs)) * 512;
#pragma unroll
            for (int jt = 0; jt < 2; jt++) {
#pragma unroll
                for (int e = 0; e < 2; e++) {
                    int j    = j0 + jw * 16 + jt * 8 + q * 2 + e;
                    int ridx = half * 2 + e;
                    float iv = acc[0][jt][ridx] + bc[0 * 512 + j];
                    float fl = acc[1][jt][ridx] + bc[1 * 512 + j];
                    float fr = acc[2][jt][ridx] + bc[2 * 512 + j];
                    float uu = acc[3][jt][ridx] + bc[3 * 512 + j];
                    float oo = acc[4][jt][ridx] + bc[4 * 512 + j];
                    float cl = g_c[ob + j], cr = g_c[rb + j];
                    float cn = cl * sigf(fl + 1.f) + cr * sigf(fr + 1.f)
                             + tanhf(uu) * sigf(iv);
                    float hn = sigf(oo) * tanhf(cn);
                    g_compc[ob + j] = cn;
                    g_comph[ob + j] = hn;
                    partial += cq[j] * hn;
                }
            }
        }
        // fixed-order reduce over the 4 q-lanes of this row
        partial += __shfl_xor_sync(0xffffffffu, partial, 1);
        partial += __shfl_xor_sync(0xffffffffu, partial, 2);
        if (q == 0 && b >= 0) {
            int ls = sls[lrow];
            g_lgpart[((b << 5) + ls) * 32 + blockIdx.y * 2 + jw] = partial;
        }
    }
}

// ---------------- select + merge (1 CTA per batch) --------------------------
__global__ __launch_bounds__(256) void select_kernel(const int* __restrict__ length,
                                                     int step) {
    int b = blockIdx.x;
    int lane = threadIdx.x & 31;
    int warp = threadIdx.x >> 5;
    __shared__ int sh_active, sh_s;

    if (warp == 0) {
        int len = length[b];
        int active = (step + 1 < len);
        int s = 0;
        if (active) {
            int n    = 32 - step;
            int vlim = len - step - 1;
            int myslot = (lane < n) ? g_order[(b << 5) + lane] : 0;

            float lg = -1e30f;
            if (lane < vlim) {            // deterministic fixed-order sum
                const float* p = &g_lgpart[((b << 5) + myslot) * 32];
                float sum = 0.f;
#pragma unroll
                for (int t = 0; t < 32; t++) sum += p[t];
                lg = sum * 0.04419417382415922f;   // 1/sqrt(512)
            }

            // argmax, first occurrence on ties (matches jnp.argmax)
            float bv = lg; int bi = lane;
#pragma unroll
            for (int off = 16; off; off >>= 1) {
                float ov = __shfl_down_sync(0xffffffffu, bv, off);
                int   oi = __shfl_down_sync(0xffffffffu, bi, off);
                if (ov > bv || (ov == bv && oi < bi)) { bv = ov; bi = oi; }
            }
            int p = __shfl_sync(0xffffffffu, bi, 0);

            s        = __shfl_sync(0xffffffffu, myslot, p);
            int prev = __shfl_sync(0xffffffffu, myslot, (p > 0) ? (p - 1) : 0);
            int nxt2 = __shfl_sync(0xffffffffu, myslot, (p + 2 <= n - 1) ? (p + 2) : 0);
            int nxt  = __shfl_down_sync(0xffffffffu, myslot, 1);

            if (lane >= p + 1 && lane <= n - 2) g_order[(b << 5) + lane] = nxt;
            if (lane == 0) {
                int4 t0 = make_int4(0, 0, 0, 0), t1 = make_int4(0, 0, 0, 0);
                if (p > 0)          t0 = make_int4(1, b, prev, s);
                if (p + 2 <= n - 1) t1 = make_int4(1, b, s, nxt2);
                g_tasks[2 * b]     = t0;
                g_tasks[2 * b + 1] = t1;
            }
        } else if (lane == 0) {
            g_tasks[2 * b]     = make_int4(0, 0, 0, 0);
            g_tasks[2 * b + 1] = make_int4(0, 0, 0, 0);
        }
        if (lane == 0) { sh_active = active; sh_s = s; }
    }
    __syncthreads();
    if (!sh_active) return;

    // merge copy: node s takes the composed value (all 256 threads)
    size_t base = ((size_t)((b << 5) + sh_s)) * 128;   // float4 units
    int t = threadIdx.x;
    if (t < 128) ((float4*)g_h)[base + t]       = ((const float4*)g_comph)[base + t];
    else         ((float4*)g_c)[base + t - 128] = ((const float4*)g_compc)[base + t - 128];
}

// ---------------- output: h of slot 0 of each batch -------------------------
__global__ void out_kernel(float* __restrict__ out) {
    int idx = blockIdx.x * 256 + threadIdx.x;   // 131072 total
    int b = idx >> 9, j = idx & 511;
    out[idx] = g_h[((size_t)b << 14) + j];      // slot 0
}

// ---------------- launch ----------------------------------------------------
extern "C" void kernel_launch(void* const* d_in, const int* in_sizes, int n_in,
                              void* d_out, int out_size) {
    const float* x      = (const float*)d_in[0];
    const int*   length = (const int*)  d_in[1];
    const float* Ww     = (const float*)d_in[2];
    const float* bw     = (const float*)d_in[3];
    const float* Wc     = (const float*)d_in[4];
    const float* bc     = (const float*)d_in[5];
    const float* cq     = (const float*)d_in[6];

    size_t shmem = (size_t)(64 * SA_STRIDE + 5 * 32 * SB_STRIDE) * sizeof(uint4)
                 + 3 * 64 * sizeof(int);
    cudaFuncSetAttribute(compose_mma, cudaFuncAttributeMaxDynamicSharedMemorySize,
                         (int)shmem);

    init_kernel<<<32, 256>>>();
    word_kernel<<<dim3(64, 8), 256>>>(x, Ww, bw);
    // initial compose of all 31 adjacent pairs per batch (7936 rows)
    compose_mma<<<dim3(124, 16), 256, shmem>>>(Wc, bc, cq, 1, 7936);
    for (int i = 0; i < 31; i++) {
        select_kernel<<<256, 256>>>(length, i);
        compose_mma<<<dim3(8, 16), 256, shmem>>>(Wc, bc, cq, 0, 512);
    }
    out_kernel<<<512, 256>>>((float*)d_out);
    (void)in_sizes; (void)n_in; (void)out_size;
}